// round 1
// baseline (speedup 1.0000x reference)
#include <cuda_runtime.h>
#include <cstdint>
#include <cstddef>

// Problem constants (shapes fixed by the dataset)
#define Nn 65536
#define Dd 256
#define Kk 4096
#define DECAYF 0.99f
#define BETAF 0.25f
#define EPSF 1e-5f

// Argmin-GEMM tiling
#define BM 128       // rows of z per block
#define KT 128       // codebook columns per k-tile
#define BD 64        // d-chunk streamed per cp.async stage
#define WBUF (BD*KT) // floats per weight buffer
#define NCHUNK ((Kk/KT)*(Dd/BD))   // 128

// -------- scratch (static device globals; no dynamic allocation) --------
__device__ __align__(16) float g_wt[(size_t)Dd * Kk];   // W transposed: [d][k]
__device__ __align__(16) float g_wsq[Kk];
__device__ __align__(16) int   g_idx[Nn];
__device__ __align__(16) float g_counts[Kk];
__device__ __align__(16) float g_dw[(size_t)Kk * Dd];
__device__ __align__(16) float g_cs[Kk];
__device__ __align__(16) float g_red[4];

// ---------------------------------------------------------------
// 1) transpose W [K][D] -> g_wt [D][K]
// ---------------------------------------------------------------
__global__ void transpose_kernel(const float* __restrict__ W) {
    __shared__ float t[32][33];
    int k0 = blockIdx.x * 32, d0 = blockIdx.y * 32;
    int x = threadIdx.x, y = threadIdx.y;   // 32 x 8
#pragma unroll
    for (int r = 0; r < 4; ++r)
        t[y + 8 * r][x] = W[(size_t)(k0 + y + 8 * r) * Dd + d0 + x];
    __syncthreads();
#pragma unroll
    for (int r = 0; r < 4; ++r)
        g_wt[(size_t)(d0 + y + 8 * r) * Kk + k0 + x] = t[x][y + 8 * r];
}

// ---------------------------------------------------------------
// 2) wsq[k] = sum_d W[k][d]^2   (one 256-thread block per row)
// ---------------------------------------------------------------
__global__ void wsq_kernel(const float* __restrict__ W) {
    __shared__ float s[8];
    int k = blockIdx.x, t = threadIdx.x;
    float v = W[(size_t)k * Dd + t];
    v *= v;
#pragma unroll
    for (int o = 16; o; o >>= 1) v += __shfl_xor_sync(0xffffffffu, v, o);
    if ((t & 31) == 0) s[t >> 5] = v;
    __syncthreads();
    if (t < 8) {
        float x = s[t];
#pragma unroll
        for (int o = 4; o; o >>= 1) x += __shfl_xor_sync(0xffu, x, o);
        if (t == 0) g_wsq[k] = x;
    }
}

// ---------------------------------------------------------------
// 3) fused distance + argmin (the heavy kernel)
//    dist(n,k) = wsq[k] - 2 * z[n].W[k]   (||z||^2 is argmin-invariant)
// ---------------------------------------------------------------
__device__ __forceinline__ void issue_chunk(float* ws, int c, int b, int tid) {
    const float* src = g_wt + (size_t)((c & 3) * BD) * Kk + (size_t)(c >> 2) * KT;
    float* dst = ws + b * WBUF;
#pragma unroll
    for (int i = 0; i < 8; ++i) {
        int q = tid + i * 256;
        int row = q >> 5, col = (q & 31) * 4;
        unsigned sa = (unsigned)__cvta_generic_to_shared(dst + row * KT + col);
        const float* gp = src + (size_t)row * Kk + col;
        asm volatile("cp.async.cg.shared.global [%0], [%1], 16;" :: "r"(sa), "l"(gp));
    }
    asm volatile("cp.async.commit_group;");
}

__global__ __launch_bounds__(256, 1)
void argmin_kernel(const float* __restrict__ z) {
    extern __shared__ float smem[];
    float* zs = smem;                 // [BM][Dd]  (128 KB)
    float* ws = smem + BM * Dd;       // [2][BD][KT] (64 KB)
    int tid = threadIdx.x;
    int tx = tid & 15, ty = tid >> 4;
    int m0 = blockIdx.x * BM;

    issue_chunk(ws, 0, 0, tid);

    // z tile -> smem, coalesced float4 copy
    const float4* zg = (const float4*)(z + (size_t)m0 * Dd);
    float4* zs4 = (float4*)zs;
#pragma unroll
    for (int i = 0; i < 32; ++i) zs4[tid + (i << 8)] = zg[tid + (i << 8)];

    // accumulators: 8 m-rows x 4 k-pairs (f32x2 packed along k)
    unsigned long long acc[8][4];
#pragma unroll
    for (int i = 0; i < 8; ++i)
#pragma unroll
        for (int j = 0; j < 4; ++j) acc[i][j] = 0ull;

    float best_v[8];
    int best_i[8];
#pragma unroll
    for (int i = 0; i < 8; ++i) { best_v[i] = 3.4e38f; best_i[i] = 0; }

    for (int c = 0; c < NCHUNK; ++c) {
        int b = c & 1;
        if (c + 1 < NCHUNK) {
            issue_chunk(ws, c + 1, b ^ 1, tid);
            asm volatile("cp.async.wait_group 1;");
        } else {
            asm volatile("cp.async.wait_group 0;");
        }
        __syncthreads();

        const float* wb = ws + b * WBUF;
        int dg0 = (c & 3) * BD;
#pragma unroll 4
        for (int d = 0; d < BD; ++d) {
            unsigned long long bf[4];
#pragma unroll
            for (int jp = 0; jp < 4; ++jp)
                bf[jp] = *(const unsigned long long*)(wb + d * KT + 2 * tx + 32 * jp);
#pragma unroll
            for (int i = 0; i < 8; ++i) {
                float a = zs[(ty * 8 + i) * Dd + dg0 + d];
                unsigned long long a2;
                asm("mov.b64 %0, {%1, %1};" : "=l"(a2) : "f"(a));
#pragma unroll
                for (int jp = 0; jp < 4; ++jp)
                    asm("fma.rn.f32x2 %0, %1, %2, %0;"
                        : "+l"(acc[i][jp]) : "l"(a2), "l"(bf[jp]));
            }
        }

        if ((c & 3) == 3) {  // finished K-tile: fold into running argmin
            int k0 = (c >> 2) * KT;
            float wq[8];
#pragma unroll
            for (int jp = 0; jp < 4; ++jp) {
                int kk = k0 + 2 * tx + 32 * jp;
                wq[2 * jp] = __ldg(&g_wsq[kk]);
                wq[2 * jp + 1] = __ldg(&g_wsq[kk + 1]);
            }
#pragma unroll
            for (int i = 0; i < 8; ++i) {
                float v = 3.4e38f; int vi = 0;
#pragma unroll
                for (int jp = 0; jp < 4; ++jp) {
                    float lo, hi;
                    asm("mov.b64 {%0, %1}, %2;" : "=f"(lo), "=f"(hi) : "l"(acc[i][jp]));
                    int kk = k0 + 2 * tx + 32 * jp;
                    float d0 = wq[2 * jp] - 2.0f * lo;
                    float d1 = wq[2 * jp + 1] - 2.0f * hi;
                    if (d0 < v) { v = d0; vi = kk; }
                    if (d1 < v) { v = d1; vi = kk + 1; }
                    acc[i][jp] = 0ull;
                }
                // reduce across the 16 k-lanes (bfly keeps all lanes consistent)
#pragma unroll
                for (int off = 8; off > 0; off >>= 1) {
                    float ov = __shfl_xor_sync(0xffffffffu, v, off);
                    int oi = __shfl_xor_sync(0xffffffffu, vi, off);
                    if (ov < v || (ov == v && oi < vi)) { v = ov; vi = oi; }
                }
                if (v < best_v[i]) { best_v[i] = v; best_i[i] = vi; }
            }
        }
        __syncthreads();
    }

    if (tx == 0) {
#pragma unroll
        for (int i = 0; i < 8; ++i) {
            int m = m0 + ty * 8 + i;
            g_idx[m] = best_i[i];
            atomicAdd(&g_counts[best_i[i]], 1.0f);
        }
    }
}

// ---------------------------------------------------------------
// 4) dw[k] += z[n] for idx[n]==k  (one warp per row)
// ---------------------------------------------------------------
__global__ void scatter_kernel(const float* __restrict__ z) {
    int n = (blockIdx.x * blockDim.x + threadIdx.x) >> 5;
    int lane = threadIdx.x & 31;
    int k = g_idx[n];
    const float* zr = z + (size_t)n * Dd;
    float* dr = g_dw + (size_t)k * Dd;
#pragma unroll
    for (int j = 0; j < 8; ++j)
        atomicAdd(dr + lane + 32 * j, zr[lane + 32 * j]);
}

// ---------------------------------------------------------------
// 5) cluster-size EMA + Laplace smoothing + perplexity (1 block)
// ---------------------------------------------------------------
__global__ void finalize_cs_kernel(const float* __restrict__ cs_in,
                                   float* __restrict__ out_cs,
                                   float* __restrict__ out_perp) {
    __shared__ float s1[256], s2[256];
    int t = threadIdx.x;
    float scs = 0.f, se = 0.f;
    float csr[16];
#pragma unroll
    for (int i = 0; i < 16; ++i) {
        int k = t + i * 256;
        float cnt = g_counts[k];
        float r = cs_in[k] * DECAYF + (1.0f - DECAYF) * cnt;
        csr[i] = r;
        scs += r;
        float p = cnt * (1.0f / (float)Nn);
        se += p * logf(p + 1e-10f);
    }
    s1[t] = scs; s2[t] = se;
    __syncthreads();
    for (int o = 128; o; o >>= 1) {
        if (t < o) { s1[t] += s1[t + o]; s2[t] += s2[t + o]; }
        __syncthreads();
    }
    float n = s1[0];
    float scale = n / (n + (float)Kk * EPSF);
#pragma unroll
    for (int i = 0; i < 16; ++i) {
        int k = t + i * 256;
        float cf = (csr[i] + EPSF) * scale;
        g_cs[k] = cf;
        out_cs[k] = cf;
    }
    if (t == 0) out_perp[0] = expf(-s2[0]);
}

// ---------------------------------------------------------------
// 6) EMA weight + normalized codebook
// ---------------------------------------------------------------
__global__ void update_w_kernel(const float* __restrict__ ema,
                                float* __restrict__ out_ema,
                                float* __restrict__ out_w) {
    int i = blockIdx.x * 256 + threadIdx.x;
    float e = ema[i] * DECAYF + (1.0f - DECAYF) * g_dw[i];
    out_ema[i] = e;
    out_w[i] = e / g_cs[i >> 8];
}

// ---------------------------------------------------------------
// 7) z_q gather (STE) + loss partial + idx as float (warp per row)
// ---------------------------------------------------------------
__global__ void gather_loss_kernel(const float* __restrict__ z,
                                   const float* __restrict__ w_new,
                                   float* __restrict__ out_zq,
                                   float* __restrict__ out_idx) {
    int n = (blockIdx.x * blockDim.x + threadIdx.x) >> 5;
    int lane = threadIdx.x & 31;
    int k = g_idx[n];
    const float* wr = w_new + (size_t)k * Dd;
    const float* zr = z + (size_t)n * Dd;
    float* qr = out_zq + (size_t)n * Dd;
    float part = 0.f;
#pragma unroll
    for (int j = 0; j < 8; ++j) {
        int dd = lane + 32 * j;
        float wv = wr[dd], zv = zr[dd];
        float tdiff = wv - zv;          // stop_gradient(z_q - z)
        qr[dd] = zv + tdiff;            // z + (z_q - z), matches jax STE arithmetic
        part += tdiff * tdiff;
    }
#pragma unroll
    for (int o = 16; o; o >>= 1) part += __shfl_xor_sync(0xffffffffu, part, o);
    if (lane == 0) {
        out_idx[n] = (float)k;
        atomicAdd(&g_red[0], part);
    }
}

__global__ void loss_kernel(float* __restrict__ out_loss) {
    out_loss[0] = (1.0f + BETAF) * g_red[0] / (float)((size_t)Nn * Dd);
}

// ---------------------------------------------------------------
// host launcher
// ---------------------------------------------------------------
extern "C" void kernel_launch(void* const* d_in, const int* in_sizes, int n_in,
                              void* d_out, int out_size) {
    const float* z   = (const float*)d_in[0];
    const float* W   = (const float*)d_in[1];
    const float* ema = (const float*)d_in[2];
    const float* cs  = (const float*)d_in[3];
    float* out = (float*)d_out;

    const size_t off_idx  = (size_t)Nn * Dd;
    const size_t off_loss = off_idx + Nn;
    const size_t off_perp = off_loss + 1;
    const size_t off_cs   = off_perp + 1;
    const size_t off_emaw = off_cs + Kk;
    const size_t off_w    = off_emaw + (size_t)Kk * Dd;

    void *p_counts, *p_dw, *p_red;
    cudaGetSymbolAddress(&p_counts, g_counts);
    cudaGetSymbolAddress(&p_dw, g_dw);
    cudaGetSymbolAddress(&p_red, g_red);
    cudaMemsetAsync(p_counts, 0, Kk * sizeof(float));
    cudaMemsetAsync(p_dw, 0, (size_t)Kk * Dd * sizeof(float));
    cudaMemsetAsync(p_red, 0, 4 * sizeof(float));

    const int smem_bytes = (BM * Dd + 2 * WBUF) * (int)sizeof(float);  // 192 KB
    cudaFuncSetAttribute(argmin_kernel, cudaFuncAttributeMaxDynamicSharedMemorySize,
                         smem_bytes);

    transpose_kernel<<<dim3(Kk / 32, Dd / 32), dim3(32, 8)>>>(W);
    wsq_kernel<<<Kk, 256>>>(W);
    argmin_kernel<<<Nn / BM, 256, smem_bytes>>>(z);
    scatter_kernel<<<Nn / 8, 256>>>(z);
    finalize_cs_kernel<<<1, 256>>>(cs, out + off_cs, out + off_perp);
    update_w_kernel<<<(Kk * Dd) / 256, 256>>>(ema, out + off_emaw, out + off_w);
    gather_loss_kernel<<<Nn / 8, 256>>>(z, out + off_w, out, out + off_idx);
    loss_kernel<<<1, 1>>>(out + off_loss);
}

// round 2
// speedup vs baseline: 1.0000x; 1.0000x over previous
#include <cuda_runtime.h>
#include <cstdint>
#include <cstddef>

// Problem constants (shapes fixed by the dataset)
#define Nn 65536
#define Dd 256
#define Kk 4096
#define DECAYF 0.99f
#define BETAF 0.25f
#define EPSF 1e-5f

// Argmin-GEMM tiling
#define BM 128       // rows of z per block
#define KT 128       // codebook columns per k-tile
#define BD 64        // d-chunk streamed per cp.async stage
#define WBUF (BD*KT) // floats per weight buffer
#define NCHUNK ((Kk/KT)*(Dd/BD))   // 128

// -------- scratch (static device globals; no dynamic allocation) --------
__device__ __align__(16) float g_wt[(size_t)Dd * Kk];   // W transposed: [d][k]
__device__ __align__(16) float g_wsq[Kk];
__device__ __align__(16) int   g_idx[Nn];
__device__ __align__(16) float g_counts[Kk];
__device__ __align__(16) float g_dw[(size_t)Kk * Dd];
__device__ __align__(16) float g_cs[Kk];
__device__ __align__(16) float g_red[4];

// ---------------------------------------------------------------
// 1) transpose W [K][D] -> g_wt [D][K]
// ---------------------------------------------------------------
__global__ void transpose_kernel(const float* __restrict__ W) {
    __shared__ float t[32][33];
    int k0 = blockIdx.x * 32, d0 = blockIdx.y * 32;
    int x = threadIdx.x, y = threadIdx.y;   // 32 x 8
#pragma unroll
    for (int r = 0; r < 4; ++r)
        t[y + 8 * r][x] = W[(size_t)(k0 + y + 8 * r) * Dd + d0 + x];
    __syncthreads();
#pragma unroll
    for (int r = 0; r < 4; ++r)
        g_wt[(size_t)(d0 + y + 8 * r) * Kk + k0 + x] = t[x][y + 8 * r];
}

// ---------------------------------------------------------------
// 2) wsq[k] = sum_d W[k][d]^2   (one 256-thread block per row)
// ---------------------------------------------------------------
__global__ void wsq_kernel(const float* __restrict__ W) {
    __shared__ float s[8];
    int k = blockIdx.x, t = threadIdx.x;
    float v = W[(size_t)k * Dd + t];
    v *= v;
#pragma unroll
    for (int o = 16; o; o >>= 1) v += __shfl_xor_sync(0xffffffffu, v, o);
    if ((t & 31) == 0) s[t >> 5] = v;
    __syncthreads();
    if (t < 8) {
        float x = s[t];
#pragma unroll
        for (int o = 4; o; o >>= 1) x += __shfl_xor_sync(0xffu, x, o);
        if (t == 0) g_wsq[k] = x;
    }
}

// ---------------------------------------------------------------
// 3) fused distance + argmin (the heavy kernel)
//    dist(n,k) = wsq[k] - 2 * z[n].W[k]   (||z||^2 is argmin-invariant)
// ---------------------------------------------------------------
__device__ __forceinline__ void issue_chunk(float* ws, int c, int b, int tid) {
    const float* src = g_wt + (size_t)((c & 3) * BD) * Kk + (size_t)(c >> 2) * KT;
    float* dst = ws + b * WBUF;
#pragma unroll
    for (int i = 0; i < 8; ++i) {
        int q = tid + i * 256;
        int row = q >> 5, col = (q & 31) * 4;
        unsigned sa = (unsigned)__cvta_generic_to_shared(dst + row * KT + col);
        const float* gp = src + (size_t)row * Kk + col;
        asm volatile("cp.async.cg.shared.global [%0], [%1], 16;" :: "r"(sa), "l"(gp));
    }
    asm volatile("cp.async.commit_group;");
}

__global__ __launch_bounds__(256, 1)
void argmin_kernel(const float* __restrict__ z) {
    extern __shared__ float smem[];
    float* zs = smem;                 // [BM][Dd]  (128 KB)
    float* ws = smem + BM * Dd;       // [2][BD][KT] (64 KB)
    int tid = threadIdx.x;
    int tx = tid & 15, ty = tid >> 4;
    int m0 = blockIdx.x * BM;

    issue_chunk(ws, 0, 0, tid);

    // z tile -> smem, coalesced float4 copy
    const float4* zg = (const float4*)(z + (size_t)m0 * Dd);
    float4* zs4 = (float4*)zs;
#pragma unroll
    for (int i = 0; i < 32; ++i) zs4[tid + (i << 8)] = zg[tid + (i << 8)];

    // accumulators: 8 m-rows x 4 k-pairs (f32x2 packed along k)
    unsigned long long acc[8][4];
#pragma unroll
    for (int i = 0; i < 8; ++i)
#pragma unroll
        for (int j = 0; j < 4; ++j) acc[i][j] = 0ull;

    float best_v[8];
    int best_i[8];
#pragma unroll
    for (int i = 0; i < 8; ++i) { best_v[i] = 3.4e38f; best_i[i] = 0; }

    for (int c = 0; c < NCHUNK; ++c) {
        int b = c & 1;
        if (c + 1 < NCHUNK) {
            issue_chunk(ws, c + 1, b ^ 1, tid);
            asm volatile("cp.async.wait_group 1;");
        } else {
            asm volatile("cp.async.wait_group 0;");
        }
        __syncthreads();

        const float* wb = ws + b * WBUF;
        int dg0 = (c & 3) * BD;
#pragma unroll 4
        for (int d = 0; d < BD; ++d) {
            unsigned long long bf[4];
#pragma unroll
            for (int jp = 0; jp < 4; ++jp)
                bf[jp] = *(const unsigned long long*)(wb + d * KT + 2 * tx + 32 * jp);
#pragma unroll
            for (int i = 0; i < 8; ++i) {
                float a = zs[(ty * 8 + i) * Dd + dg0 + d];
                unsigned long long a2;
                asm("mov.b64 %0, {%1, %1};" : "=l"(a2) : "f"(a));
#pragma unroll
                for (int jp = 0; jp < 4; ++jp)
                    asm("fma.rn.f32x2 %0, %1, %2, %0;"
                        : "+l"(acc[i][jp]) : "l"(a2), "l"(bf[jp]));
            }
        }

        if ((c & 3) == 3) {  // finished K-tile: fold into running argmin
            int k0 = (c >> 2) * KT;
            float wq[8];
#pragma unroll
            for (int jp = 0; jp < 4; ++jp) {
                int kk = k0 + 2 * tx + 32 * jp;
                wq[2 * jp] = __ldg(&g_wsq[kk]);
                wq[2 * jp + 1] = __ldg(&g_wsq[kk + 1]);
            }
#pragma unroll
            for (int i = 0; i < 8; ++i) {
                float v = 3.4e38f; int vi = 0;
#pragma unroll
                for (int jp = 0; jp < 4; ++jp) {
                    float lo, hi;
                    asm("mov.b64 {%0, %1}, %2;" : "=f"(lo), "=f"(hi) : "l"(acc[i][jp]));
                    int kk = k0 + 2 * tx + 32 * jp;
                    float d0 = wq[2 * jp] - 2.0f * lo;
                    float d1 = wq[2 * jp + 1] - 2.0f * hi;
                    if (d0 < v) { v = d0; vi = kk; }
                    if (d1 < v) { v = d1; vi = kk + 1; }
                    acc[i][jp] = 0ull;
                }
                // reduce across the 16 k-lanes (bfly keeps all lanes consistent)
#pragma unroll
                for (int off = 8; off > 0; off >>= 1) {
                    float ov = __shfl_xor_sync(0xffffffffu, v, off);
                    int oi = __shfl_xor_sync(0xffffffffu, vi, off);
                    if (ov < v || (ov == v && oi < vi)) { v = ov; vi = oi; }
                }
                if (v < best_v[i]) { best_v[i] = v; best_i[i] = vi; }
            }
        }
        __syncthreads();
    }

    if (tx == 0) {
#pragma unroll
        for (int i = 0; i < 8; ++i) {
            int m = m0 + ty * 8 + i;
            g_idx[m] = best_i[i];
            atomicAdd(&g_counts[best_i[i]], 1.0f);
        }
    }
}

// ---------------------------------------------------------------
// 4) dw[k] += z[n] for idx[n]==k  (one warp per row)
// ---------------------------------------------------------------
__global__ void scatter_kernel(const float* __restrict__ z) {
    int n = (blockIdx.x * blockDim.x + threadIdx.x) >> 5;
    int lane = threadIdx.x & 31;
    int k = g_idx[n];
    const float* zr = z + (size_t)n * Dd;
    float* dr = g_dw + (size_t)k * Dd;
#pragma unroll
    for (int j = 0; j < 8; ++j)
        atomicAdd(dr + lane + 32 * j, zr[lane + 32 * j]);
}

// ---------------------------------------------------------------
// 5) cluster-size EMA + Laplace smoothing + perplexity (1 block)
// ---------------------------------------------------------------
__global__ void finalize_cs_kernel(const float* __restrict__ cs_in,
                                   float* __restrict__ out_cs,
                                   float* __restrict__ out_perp) {
    __shared__ float s1[256], s2[256];
    int t = threadIdx.x;
    float scs = 0.f, se = 0.f;
    float csr[16];
#pragma unroll
    for (int i = 0; i < 16; ++i) {
        int k = t + i * 256;
        float cnt = g_counts[k];
        float r = cs_in[k] * DECAYF + (1.0f - DECAYF) * cnt;
        csr[i] = r;
        scs += r;
        float p = cnt * (1.0f / (float)Nn);
        se += p * logf(p + 1e-10f);
    }
    s1[t] = scs; s2[t] = se;
    __syncthreads();
    for (int o = 128; o; o >>= 1) {
        if (t < o) { s1[t] += s1[t + o]; s2[t] += s2[t + o]; }
        __syncthreads();
    }
    float n = s1[0];
    float scale = n / (n + (float)Kk * EPSF);
#pragma unroll
    for (int i = 0; i < 16; ++i) {
        int k = t + i * 256;
        float cf = (csr[i] + EPSF) * scale;
        g_cs[k] = cf;
        out_cs[k] = cf;
    }
    if (t == 0) out_perp[0] = expf(-s2[0]);
}

// ---------------------------------------------------------------
// 6) EMA weight + normalized codebook
// ---------------------------------------------------------------
__global__ void update_w_kernel(const float* __restrict__ ema,
                                float* __restrict__ out_ema,
                                float* __restrict__ out_w) {
    int i = blockIdx.x * 256 + threadIdx.x;
    float e = ema[i] * DECAYF + (1.0f - DECAYF) * g_dw[i];
    out_ema[i] = e;
    out_w[i] = e / g_cs[i >> 8];
}

// ---------------------------------------------------------------
// 7) z_q gather (STE) + loss partial + idx as float (warp per row)
// ---------------------------------------------------------------
__global__ void gather_loss_kernel(const float* __restrict__ z,
                                   const float* __restrict__ w_new,
                                   float* __restrict__ out_zq,
                                   float* __restrict__ out_idx) {
    int n = (blockIdx.x * blockDim.x + threadIdx.x) >> 5;
    int lane = threadIdx.x & 31;
    int k = g_idx[n];
    const float* wr = w_new + (size_t)k * Dd;
    const float* zr = z + (size_t)n * Dd;
    float* qr = out_zq + (size_t)n * Dd;
    float part = 0.f;
#pragma unroll
    for (int j = 0; j < 8; ++j) {
        int dd = lane + 32 * j;
        float wv = wr[dd], zv = zr[dd];
        float tdiff = wv - zv;          // stop_gradient(z_q - z)
        qr[dd] = zv + tdiff;            // z + (z_q - z), matches jax STE arithmetic
        part += tdiff * tdiff;
    }
#pragma unroll
    for (int o = 16; o; o >>= 1) part += __shfl_xor_sync(0xffffffffu, part, o);
    if (lane == 0) {
        out_idx[n] = (float)k;
        atomicAdd(&g_red[0], part);
    }
}

__global__ void loss_kernel(float* __restrict__ out_loss) {
    out_loss[0] = (1.0f + BETAF) * g_red[0] / (float)((size_t)Nn * Dd);
}

// ---------------------------------------------------------------
// host launcher
// ---------------------------------------------------------------
extern "C" void kernel_launch(void* const* d_in, const int* in_sizes, int n_in,
                              void* d_out, int out_size) {
    const float* z   = (const float*)d_in[0];
    const float* W   = (const float*)d_in[1];
    const float* ema = (const float*)d_in[2];
    const float* cs  = (const float*)d_in[3];
    float* out = (float*)d_out;

    const size_t off_idx  = (size_t)Nn * Dd;
    const size_t off_loss = off_idx + Nn;
    const size_t off_perp = off_loss + 1;
    const size_t off_cs   = off_perp + 1;
    const size_t off_emaw = off_cs + Kk;
    const size_t off_w    = off_emaw + (size_t)Kk * Dd;

    void *p_counts, *p_dw, *p_red;
    cudaGetSymbolAddress(&p_counts, g_counts);
    cudaGetSymbolAddress(&p_dw, g_dw);
    cudaGetSymbolAddress(&p_red, g_red);
    cudaMemsetAsync(p_counts, 0, Kk * sizeof(float));
    cudaMemsetAsync(p_dw, 0, (size_t)Kk * Dd * sizeof(float));
    cudaMemsetAsync(p_red, 0, 4 * sizeof(float));

    const int smem_bytes = (BM * Dd + 2 * WBUF) * (int)sizeof(float);  // 192 KB
    cudaFuncSetAttribute(argmin_kernel, cudaFuncAttributeMaxDynamicSharedMemorySize,
                         smem_bytes);

    transpose_kernel<<<dim3(Kk / 32, Dd / 32), dim3(32, 8)>>>(W);
    wsq_kernel<<<Kk, 256>>>(W);
    argmin_kernel<<<Nn / BM, 256, smem_bytes>>>(z);
    scatter_kernel<<<Nn / 8, 256>>>(z);
    finalize_cs_kernel<<<1, 256>>>(cs, out + off_cs, out + off_perp);
    update_w_kernel<<<(Kk * Dd) / 256, 256>>>(ema, out + off_emaw, out + off_w);
    gather_loss_kernel<<<Nn / 8, 256>>>(z, out + off_w, out, out + off_idx);
    loss_kernel<<<1, 1>>>(out + off_loss);
}